// round 14
// baseline (speedup 1.0000x reference)
#include <cuda_runtime.h>
#include <math.h>
#include <stdint.h>

#define HEADS   8
#define DIMV    384
#define HD      48
#define ADLAV   343
#define HWD     14
#define NTOK    2744
#define BATCH   8
#define SCALEV  0.14433756729740645f   // 48^-0.5
#define NSPLIT  8
#define QKVS    1152                   // packed qkv row stride

#define BN_TOT  (BATCH * NTOK)         // 21952
#define BH      (BATCH * HEADS)        // 64

// ---------------- scratch (static device allocations) ------------------------
__device__ float g_qkv[BATCH * NTOK * QKVS];         // [b,n, q(384)|k(384)|v(384)]
__device__ float g_wqkv[DIMV * QKVS];                // packed [Wq|Wkv]
__device__ float g_adla[BATCH * ADLAV * DIMV];
__device__ float g_bias1[HEADS * ADLAV * NTOK];
__device__ float g_bias2[HEADS * ADLAV * NTOK];      // [h,a,n]
__device__ float g_bias2t[HEADS * ADLAV * NTOK];     // [h,n,a]
__device__ float g_adlav[BATCH * HEADS * ADLAV * HD];
__device__ float g_avp[NSPLIT * BH * ADLAV * HD];    // split partial O~
__device__ float g_lsp[NSPLIT * BH * ADLAV];         // split partial rowsum
__device__ float g_attnout[BATCH * NTOK * DIMV];

// ---------------- tf32 helpers ----------------------------------------------
__device__ __forceinline__ uint32_t f2tf32(float x) {
    uint32_t r;
    asm("cvt.rna.tf32.f32 %0, %1;" : "=r"(r) : "f"(x));
    return r;
}

__device__ __forceinline__ void mma_tf32(float* c, const uint32_t* a, const uint32_t* b) {
    asm volatile(
        "mma.sync.aligned.m16n8k8.row.col.f32.tf32.tf32.f32 "
        "{%0,%1,%2,%3}, {%4,%5,%6,%7}, {%8,%9}, {%0,%1,%2,%3};\n"
        : "+f"(c[0]), "+f"(c[1]), "+f"(c[2]), "+f"(c[3])
        : "r"(a[0]), "r"(a[1]), "r"(a[2]), "r"(a[3]), "r"(b[0]), "r"(b[1]));
}

// ============ fused attention core (no max subtraction) ======================
#define KSP 72
#define VSP 56
#define PSP 24
#define FSM ((48*KSP + 64*VSP + 8*64*PSP) * 4)

template<int PARTIAL>
__global__ __launch_bounds__(256) void flash_core(
    const float* __restrict__ Qp, long long qB, long long qH, int qR,
    const float* __restrict__ Kp, long long kB, long long kH, int kR,
    const float* __restrict__ Vp, long long vB, long long vH, int vR, int vC,
    const float* __restrict__ Bp, long long bHs, int bR,
    float* __restrict__ Op, long long oB, long long oH, int oR,
    float* __restrict__ Lp,
    int M, int NK)
{
    extern __shared__ float sm[];
    float* Ks = sm;
    float* Vs = sm + 48 * KSP;
    float* Ps = sm + 48 * KSP + 64 * VSP;

    int bh = blockIdx.y;
    int bb = bh >> 3, hh = bh & 7;
    int m0 = blockIdx.x * 128;
    const float* Qb = Qp + bb * qB + hh * qH;
    const float* Kb = Kp + bb * kB + hh * kH;
    const float* Vb = Vp + bb * vB + hh * vH + vC;
    const float* Bb = Bp + hh * bHs;

    int tid = threadIdx.x, warp = tid >> 5, lane = tid & 31;
    int g = lane >> 2, tg = lane & 3;
    int r0 = m0 + warp * 16 + g;
    int r1 = r0 + 8;

    uint32_t qf[6][4];
    #pragma unroll
    for (int ks = 0; ks < 6; ks++) {
        int k0 = ks * 8 + tg, k1 = k0 + 4;
        qf[ks][0] = (r0 < M) ? f2tf32(Qb[(long long)r0 * qR + k0]) : 0u;
        qf[ks][1] = (r1 < M) ? f2tf32(Qb[(long long)r1 * qR + k0]) : 0u;
        qf[ks][2] = (r0 < M) ? f2tf32(Qb[(long long)r0 * qR + k1]) : 0u;
        qf[ks][3] = (r1 < M) ? f2tf32(Qb[(long long)r1 * qR + k1]) : 0u;
    }

    float oacc[6][4];
    #pragma unroll
    for (int i = 0; i < 6; i++)
        #pragma unroll
        for (int j = 0; j < 4; j++) oacc[i][j] = 0.f;
    float rs0 = 0.f, rs1 = 0.f;

    float* Pw = Ps + warp * (64 * PSP);
    int nn = tid >> 2, f0 = tid & 3;
    int nch = (NK + 63) >> 6;

    int chBegin = PARTIAL ? (int)blockIdx.z : 0;
    int chStep  = PARTIAL ? NSPLIT : 1;

    for (int ch = chBegin; ch < nch; ch += chStep) {
        int n0 = ch * 64;
        int lim = min(64, NK - n0);

        __syncthreads();
        #pragma unroll
        for (int j = 0; j < 3; j++) {
            int dbase = (f0 + j * 4) * 4;
            float4 v = make_float4(0.f, 0.f, 0.f, 0.f);
            float4 w = make_float4(0.f, 0.f, 0.f, 0.f);
            if (nn < lim) {
                v = *(const float4*)(Kb + (long long)(n0 + nn) * kR + dbase);
                w = *(const float4*)(Vb + (long long)(n0 + nn) * vR + dbase);
            }
            Ks[(dbase + 0) * KSP + nn] = __uint_as_float(f2tf32(v.x));
            Ks[(dbase + 1) * KSP + nn] = __uint_as_float(f2tf32(v.y));
            Ks[(dbase + 2) * KSP + nn] = __uint_as_float(f2tf32(v.z));
            Ks[(dbase + 3) * KSP + nn] = __uint_as_float(f2tf32(v.w));
            uint4 u;
            u.x = f2tf32(w.x); u.y = f2tf32(w.y); u.z = f2tf32(w.z); u.w = f2tf32(w.w);
            *(uint4*)&Vs[nn * VSP + dbase] = u;
        }
        __syncthreads();

        float s[8][4];
        #pragma unroll
        for (int ni = 0; ni < 8; ni++)
            #pragma unroll
            for (int l = 0; l < 4; l++) s[ni][l] = 0.f;
        #pragma unroll
        for (int ks = 0; ks < 6; ks++) {
            #pragma unroll
            for (int ni = 0; ni < 8; ni++) {
                uint32_t bf[2];
                bf[0] = __float_as_uint(Ks[(ks * 8 + tg) * KSP + ni * 8 + g]);
                bf[1] = __float_as_uint(Ks[(ks * 8 + tg + 4) * KSP + ni * 8 + g]);
                mma_tf32(s[ni], qf[ks], bf);
            }
        }
        #pragma unroll
        for (int ni = 0; ni < 8; ni++) {
            int c0 = n0 + ni * 8 + 2 * tg;
            bool v0 = c0 < NK, v1 = (c0 + 1) < NK;
            float b00 = 0.f, b01 = 0.f, b10 = 0.f, b11 = 0.f;
            if (r0 < M) {
                if (v0) b00 = Bb[(long long)r0 * bR + c0];
                if (v1) b01 = Bb[(long long)r0 * bR + c0 + 1];
            }
            if (r1 < M) {
                if (v0) b10 = Bb[(long long)r1 * bR + c0];
                if (v1) b11 = Bb[(long long)r1 * bR + c0 + 1];
            }
            s[ni][0] = v0 ? SCALEV * s[ni][0] + b00 : -1e30f;
            s[ni][1] = v1 ? SCALEV * s[ni][1] + b01 : -1e30f;
            s[ni][2] = v0 ? SCALEV * s[ni][2] + b10 : -1e30f;
            s[ni][3] = v1 ? SCALEV * s[ni][3] + b11 : -1e30f;
        }

        #pragma unroll
        for (int ni = 0; ni < 8; ni++) {
            float p0 = __expf(s[ni][0]);
            float p1 = __expf(s[ni][1]);
            float p2 = __expf(s[ni][2]);
            float p3 = __expf(s[ni][3]);
            s[ni][0] = p0; s[ni][1] = p1; s[ni][2] = p2; s[ni][3] = p3;
            rs0 += p0 + p1;
            rs1 += p2 + p3;
        }

        #pragma unroll
        for (int ni = 0; ni < 8; ni++) {
            int c = ni * 8 + 2 * tg;
            Pw[c * PSP + g]           = __uint_as_float(f2tf32(s[ni][0]));
            Pw[(c + 1) * PSP + g]     = __uint_as_float(f2tf32(s[ni][1]));
            Pw[c * PSP + g + 8]       = __uint_as_float(f2tf32(s[ni][2]));
            Pw[(c + 1) * PSP + g + 8] = __uint_as_float(f2tf32(s[ni][3]));
        }
        __syncwarp();

        #pragma unroll
        for (int ks = 0; ks < 8; ks++) {
            uint32_t af[4];
            af[0] = __float_as_uint(Pw[(ks * 8 + tg) * PSP + g]);
            af[1] = __float_as_uint(Pw[(ks * 8 + tg) * PSP + g + 8]);
            af[2] = __float_as_uint(Pw[(ks * 8 + tg + 4) * PSP + g]);
            af[3] = __float_as_uint(Pw[(ks * 8 + tg + 4) * PSP + g + 8]);
            #pragma unroll
            for (int ni = 0; ni < 6; ni++) {
                uint32_t bf[2];
                bf[0] = __float_as_uint(Vs[(ks * 8 + tg) * VSP + ni * 8 + g]);
                bf[1] = __float_as_uint(Vs[(ks * 8 + tg + 4) * VSP + ni * 8 + g]);
                mma_tf32(oacc[ni], af, bf);
            }
        }
    }

    rs0 += __shfl_xor_sync(0xffffffffu, rs0, 1);
    rs0 += __shfl_xor_sync(0xffffffffu, rs0, 2);
    rs1 += __shfl_xor_sync(0xffffffffu, rs1, 1);
    rs1 += __shfl_xor_sync(0xffffffffu, rs1, 2);

    if (PARTIAL) {
        long long rbase = ((long long)blockIdx.z * gridDim.y + bh) * M;
        float* Pop = Op + rbase * HD;
        float* Plp = Lp + rbase;
        #pragma unroll
        for (int ni = 0; ni < 6; ni++) {
            int d = ni * 8 + tg * 2;
            if (r0 < M) {
                float2 w; w.x = oacc[ni][0]; w.y = oacc[ni][1];
                *(float2*)(Pop + (long long)r0 * HD + d) = w;
            }
            if (r1 < M) {
                float2 w; w.x = oacc[ni][2]; w.y = oacc[ni][3];
                *(float2*)(Pop + (long long)r1 * HD + d) = w;
            }
        }
        if (tg == 0) {
            if (r0 < M) Plp[r0] = rs0;
            if (r1 < M) Plp[r1] = rs1;
        }
    } else {
        float* Ob = Op + bb * oB + hh * oH;
        float inv0 = 1.f / rs0;
        float inv1 = 1.f / rs1;
        #pragma unroll
        for (int ni = 0; ni < 6; ni++) {
            int d = ni * 8 + tg * 2;
            if (r0 < M) {
                float2 w; w.x = oacc[ni][0] * inv0; w.y = oacc[ni][1] * inv0;
                *(float2*)(Ob + (long long)r0 * oR + d) = w;
            }
            if (r1 < M) {
                float2 w; w.x = oacc[ni][2] * inv1; w.y = oacc[ni][3] * inv1;
                *(float2*)(Ob + (long long)r1 * oR + d) = w;
            }
        }
    }
}

// combine split partials (fixed order -> deterministic)
__global__ void combine_av(const float* __restrict__ Pop,
                           const float* __restrict__ Plp,
                           float* __restrict__ av)
{
    long long t = (long long)blockIdx.x * blockDim.x + threadIdx.x;
    if (t >= (long long)BH * ADLAV * HD) return;
    int d = (int)(t % HD);
    long long ra = t / HD;
    float so = 0.f, sl = 0.f;
    #pragma unroll
    for (int s = 0; s < NSPLIT; s++) {
        so += Pop[((long long)s * BH * ADLAV + ra) * HD + d];
        sl += Plp[(long long)s * BH * ADLAV + ra];
    }
    av[t] = so / sl;
}

// ============ tgemm128: 128x128 tile; A fragments via LDS64 (perm layout) ====
#define BMT 128
#define BNT2 128
#define BKT 16
#define PP  136
__global__ __launch_bounds__(256) void tgemm128(int M, int N, int K,
    const float* __restrict__ A, long long rsA, long long csA,
    const float* __restrict__ B, long long rsB, long long csB,
    float* __restrict__ C, long long rsC, long long csC,
    const float* __restrict__ Bi, long long rsBi, long long csBi,
    float alpha)
{
    __shared__ uint32_t As[2][BKT][PP];
    __shared__ uint32_t Bs[2][BKT][PP];

    const float* Ab = A;
    const float* Bb = B;
    float*       Cb = C;
    const float* Bib = Bi;

    int m0 = blockIdx.y * BMT;
    int n0 = blockIdx.x * BNT2;
    int tid  = threadIdx.x;
    int warp = tid >> 5;
    int lane = tid & 31;
    int g  = lane >> 2;
    int tg = lane & 3;
    int wm = warp & 1;
    int wn = warp >> 1;
    int mW = wm * 64;
    int nW = wn * 32;

    int amM = tid & 127;
    int akq = tid >> 7;
    // permuted A column: pairs (g, g+8) adjacent -> LDS64 fragment loads
    int aPerm = (amM & ~15) | ((amM & 7) << 1) | ((amM >> 3) & 1);
    const bool bContigN = (csB == 1);

    float acc[4][4][4];
    #pragma unroll
    for (int i = 0; i < 4; i++)
        #pragma unroll
        for (int j = 0; j < 4; j++)
            #pragma unroll
            for (int l = 0; l < 4; l++) acc[i][j][l] = 0.f;

    float4 va[2], vb[2];

    auto loadTile = [&](int k0) {
        #pragma unroll
        for (int i = 0; i < 2; i++) {
            int kq = akq + i * 2;
            int gm = m0 + amM, gk = k0 + kq * 4;
            float4 v = make_float4(0.f, 0.f, 0.f, 0.f);
            if (gm < M) {
                if (csA == 1 && gk + 4 <= K) {
                    v = *(const float4*)(Ab + (long long)gm * rsA + gk);
                } else {
                    float* pv = (float*)&v;
                    #pragma unroll
                    for (int j = 0; j < 4; j++)
                        if (gk + j < K) pv[j] = Ab[(long long)gm * rsA + (long long)(gk + j) * csA];
                }
            }
            va[i] = v;
        }
        #pragma unroll
        for (int i = 0; i < 2; i++) {
            int slot = tid + i * 256;
            float4 v = make_float4(0.f, 0.f, 0.f, 0.f);
            if (bContigN) {
                int kk = slot >> 5, nq = slot & 31;
                int gk = k0 + kk, gn = n0 + nq * 4;
                if (gk < K) {
                    if (gn + 4 <= N) {
                        v = *(const float4*)(Bb + (long long)gk * rsB + gn);
                    } else {
                        float* pv = (float*)&v;
                        #pragma unroll
                        for (int j = 0; j < 4; j++)
                            if (gn + j < N) pv[j] = Bb[(long long)gk * rsB + (long long)(gn + j)];
                    }
                }
            } else {
                int nnn = slot >> 2, kq2 = slot & 3;
                int gn = n0 + nnn, gk = k0 + kq2 * 4;
                if (gn < N) {
                    if (rsB == 1 && gk + 4 <= K) {
                        v = *(const float4*)(Bb + (long long)gn * csB + gk);
                    } else {
                        float* pv = (float*)&v;
                        #pragma unroll
                        for (int j = 0; j < 4; j++)
                            if (gk + j < K) pv[j] = Bb[(long long)(gk + j) * rsB + (long long)gn * csB];
                    }
                }
            }
            vb[i] = v;
        }
    };

    auto storeTile = [&](int bsel) {
        #pragma unroll
        for (int i = 0; i < 2; i++) {
            int kq = akq + i * 2;
            const float* pv = (const float*)&va[i];
            #pragma unroll
            for (int j = 0; j < 4; j++)
                As[bsel][kq * 4 + j][aPerm] = f2tf32(pv[j]);
        }
        #pragma unroll
        for (int i = 0; i < 2; i++) {
            int slot = tid + i * 256;
            const float* pv = (const float*)&vb[i];
            if (bContigN) {
                int kk = slot >> 5, nq = slot & 31;
                uint4 u;
                u.x = f2tf32(pv[0]); u.y = f2tf32(pv[1]);
                u.z = f2tf32(pv[2]); u.w = f2tf32(pv[3]);
                *(uint4*)&Bs[bsel][kk][nq * 4] = u;
            } else {
                int nnn = slot >> 2, kq2 = slot & 3;
                #pragma unroll
                for (int j = 0; j < 4; j++)
                    Bs[bsel][kq2 * 4 + j][nnn] = f2tf32(pv[j]);
            }
        }
    };

    auto compute = [&](int bsel) {
        #pragma unroll
        for (int ks = 0; ks < 2; ks++) {
            int kk = ks * 8;
            uint32_t af[4][4];
            #pragma unroll
            for (int mi = 0; mi < 4; mi++) {
                int mb = mW + mi * 16 + 2 * g;   // permuted: pair (g, g+8) adjacent
                uint2 lo = *(const uint2*)&As[bsel][kk + tg][mb];
                uint2 hi = *(const uint2*)&As[bsel][kk + tg + 4][mb];
                af[mi][0] = lo.x; af[mi][1] = lo.y;
                af[mi][2] = hi.x; af[mi][3] = hi.y;
            }
            uint32_t bf[4][2];
            #pragma unroll
            for (int ni = 0; ni < 4; ni++) {
                int nb = nW + ni * 8;
                bf[ni][0] = Bs[bsel][kk + tg][nb + g];
                bf[ni][1] = Bs[bsel][kk + tg + 4][nb + g];
            }
            #pragma unroll
            for (int mi = 0; mi < 4; mi++)
                #pragma unroll
                for (int ni = 0; ni < 4; ni++)
                    mma_tf32(acc[mi][ni], af[mi], bf[ni]);
        }
    };

    int nk = (K + BKT - 1) / BKT;
    loadTile(0);
    storeTile(0);
    __syncthreads();
    int buf = 0;
    for (int i = 0; i < nk; i++) {
        if (i + 1 < nk) loadTile((i + 1) * BKT);
        compute(buf);
        if (i + 1 < nk) {
            storeTile(buf ^ 1);
            buf ^= 1;
            __syncthreads();
        }
    }

    bool vecC = (csC == 1) && ((rsC & 1) == 0);
    #pragma unroll
    for (int mi = 0; mi < 4; mi++) {
        #pragma unroll
        for (int ni = 0; ni < 4; ni++) {
            #pragma unroll
            for (int half = 0; half < 2; half++) {
                int r = m0 + mW + mi * 16 + g + half * 8;
                if (r >= M) continue;
                int c = n0 + nW + ni * 8 + tg * 2;
                float v0 = alpha * acc[mi][ni][half * 2];
                float v1 = alpha * acc[mi][ni][half * 2 + 1];
                if (Bib) {
                    if (c < N)     v0 += Bib[(long long)r * rsBi + (long long)c * csBi];
                    if (c + 1 < N) v1 += Bib[(long long)r * rsBi + (long long)(c + 1) * csBi];
                }
                if (vecC && c + 2 <= N) {
                    float2 w; w.x = v0; w.y = v1;
                    *(float2*)(Cb + (long long)r * rsC + c) = w;
                } else {
                    if (c < N)     Cb[(long long)r * rsC + (long long)c * csC] = v0;
                    if (c + 1 < N) Cb[(long long)r * rsC + (long long)(c + 1) * csC] = v1;
                }
            }
        }
    }
}

// ---------------- pack [Wq|Wkv] -> wqkv [384][1152] ---------------------------
__global__ void pack_w(const float* __restrict__ Wq, const float* __restrict__ Wkv,
                       float* __restrict__ Wo)
{
    int t = blockIdx.x * blockDim.x + threadIdx.x;
    if (t >= DIMV * QKVS) return;
    int k = t / QKVS, c = t % QKVS;
    Wo[t] = (c < DIMV) ? Wq[k * DIMV + c] : Wkv[k * 2 * DIMV + (c - DIMV)];
}

// ---------------- pooling (qkv layout) ----------------------------------------
__global__ void pool_kernel(const float* __restrict__ qkv, float* __restrict__ adla)
{
    long long t = (long long)blockIdx.x * blockDim.x + threadIdx.x;
    if (t >= (long long)BATCH * ADLAV * DIMV) return;
    int c = (int)(t % DIMV);
    int a = (int)((t / DIMV) % ADLAV);
    int b = (int)(t / ((long long)DIMV * ADLAV));
    int p0 = a / 49, p1 = (a / 7) % 7, p2 = a % 7;
    float s = 0.f;
    #pragma unroll
    for (int r0 = 0; r0 < 2; r0++)
        #pragma unroll
        for (int r1 = 0; r1 < 2; r1++)
            #pragma unroll
            for (int r2 = 0; r2 < 2; r2++) {
                int i = p0 * 2 + r0, j = p1 * 2 + r1, k = p2 * 2 + r2;
                int n = (i * HWD + j) * HWD + k;
                s += qkv[((long long)b * NTOK + n) * QKVS + c];
            }
    adla[t] = s * 0.125f;
}

// ---------------- trilinear weights (7 -> 14) --------------------------------
__device__ __forceinline__ void lin_w(int o, int& x0, int& x1, float& w)
{
    float x = 0.5f * (float)o - 0.25f;
    x = fminf(fmaxf(x, 0.f), 6.f);
    x0 = (int)floorf(x);
    if (x0 > 6) x0 = 6;
    x1 = min(x0 + 1, 6);
    w = x - (float)x0;
}

__global__ void biasprep(const float* __restrict__ an, const float* __restrict__ na,
                         const float* __restrict__ ah, const float* __restrict__ aw,
                         const float* __restrict__ ad, const float* __restrict__ ha,
                         const float* __restrict__ wa, const float* __restrict__ da,
                         float* __restrict__ b1, float* __restrict__ b2)
{
    int haid = blockIdx.x;
    int h = haid / ADLAV;
    int a = haid % ADLAV;
    __shared__ float s_an[343], s_na[343];
    __shared__ float s_ax[3][14];
    __shared__ float s_xa[3][14];
    int tid = threadIdx.x;
    const float* anb = an + (long long)haid * 343;
    const float* nab = na + (long long)haid * 343;
    for (int i = tid; i < 343; i += 256) { s_an[i] = anb[i]; s_na[i] = nab[i]; }
    if (tid < 14) {
        s_ax[0][tid] = ah[(long long)haid * HWD + tid];
        s_ax[1][tid] = aw[(long long)haid * HWD + tid];
        s_ax[2][tid] = ad[(long long)haid * HWD + tid];
        s_xa[0][tid] = ha[((long long)h * HWD + tid) * ADLAV + a];
        s_xa[1][tid] = wa[((long long)h * HWD + tid) * ADLAV + a];
        s_xa[2][tid] = da[((long long)h * HWD + tid) * ADLAV + a];
    }
    __syncthreads();
    long long base = (long long)haid * NTOK;
    for (int n = tid; n < NTOK; n += 256) {
        int i = n / (HWD * HWD), j = (n / HWD) % HWD, k = n % HWD;
        int i0, i1, j0, j1, k0, k1;
        float wi, wj, wk;
        lin_w(i, i0, i1, wi);
        lin_w(j, j0, j1, wj);
        lin_w(k, k0, k1, wk);
        float v1, v2;
        {
            const float* t = s_an;
            float c00 = (1.f-wk)*t[(i0*7+j0)*7+k0] + wk*t[(i0*7+j0)*7+k1];
            float c01 = (1.f-wk)*t[(i0*7+j1)*7+k0] + wk*t[(i0*7+j1)*7+k1];
            float c10 = (1.f-wk)*t[(i1*7+j0)*7+k0] + wk*t[(i1*7+j0)*7+k1];
            float c11 = (1.f-wk)*t[(i1*7+j1)*7+k0] + wk*t[(i1*7+j1)*7+k1];
            v1 = (1.f-wi)*((1.f-wj)*c00 + wj*c01) + wi*((1.f-wj)*c10 + wj*c11);
        }
        {
            const float* t = s_na;
            float c00 = (1.f-wk)*t[(i0*7+j0)*7+k0] + wk*t[(i0*7+j0)*7+k1];
            float c01 = (1.f-wk)*t[(i0*7+j1)*7+k0] + wk*t[(i0*7+j1)*7+k1];
            float c10 = (1.f-wk)*t[(i1*7+j0)*7+k0] + wk*t[(i1*7+j0)*7+k1];
            float c11 = (1.f-wk)*t[(i1*7+j1)*7+k0] + wk*t[(i1*7+j1)*7+k1];
            v2 = (1.f-wi)*((1.f-wj)*c00 + wj*c01) + wi*((1.f-wj)*c10 + wj*c11);
        }
        v1 += s_ax[0][i] + s_ax[1][j] + s_ax[2][k];
        v2 += s_xa[0][i] + s_xa[1][j] + s_xa[2][k];
        b1[base + n] = v1;
        b2[base + n] = v2;
    }
}

// tiled transpose: b2[h,a,n] -> b2t[h,n,a]
__global__ void transpose_b2(const float* __restrict__ b2, float* __restrict__ b2t)
{
    __shared__ float t[32][33];
    int h = blockIdx.z;
    int a0 = blockIdx.y * 32, n0 = blockIdx.x * 32;
    int x = threadIdx.x, y = threadIdx.y;
    #pragma unroll
    for (int yy = y; yy < 32; yy += 8) {
        int a = a0 + yy, n = n0 + x;
        if (a < ADLAV && n < NTOK)
            t[yy][x] = b2[((long long)h * ADLAV + a) * NTOK + n];
    }
    __syncthreads();
    #pragma unroll
    for (int yy = y; yy < 32; yy += 8) {
        int n = n0 + yy, a = a0 + x;
        if (a < ADLAV && n < NTOK)
            b2t[((long long)h * NTOK + n) * ADLAV + a] = t[x][yy];
    }
}

// ---------------- depthwise 3x3x3 conv (SAME), add into out ------------------
__global__ void dwc_add(const float* __restrict__ qkv, const float* __restrict__ w,
                        const float* __restrict__ bvec, float* __restrict__ out)
{
    long long t = (long long)blockIdx.x * blockDim.x + threadIdx.x;
    if (t >= (long long)BATCH * NTOK * DIMV) return;
    int c = (int)(t % DIMV);
    int n = (int)((t / DIMV) % NTOK);
    int b = (int)(t / ((long long)DIMV * NTOK));
    int i = n / (HWD * HWD), j = (n / HWD) % HWD, k = n % HWD;
    float acc = bvec[c];
    const float* wc = w + (long long)c * 27;
    #pragma unroll
    for (int di = -1; di <= 1; di++) {
        int ii = i + di;
        if (ii < 0 || ii >= HWD) continue;
        #pragma unroll
        for (int dj = -1; dj <= 1; dj++) {
            int jj = j + dj;
            if (jj < 0 || jj >= HWD) continue;
            #pragma unroll
            for (int dk = -1; dk <= 1; dk++) {
                int kk = k + dk;
                if (kk < 0 || kk >= HWD) continue;
                int nn = (ii * HWD + jj) * HWD + kk;
                acc += qkv[((long long)b * NTOK + nn) * QKVS + 2 * DIMV + c]
                     * wc[(di + 1) * 9 + (dj + 1) * 3 + (dk + 1)];
            }
        }
    }
    out[t] += acc;
}

// ---------------- host launcher ----------------------------------------------
static inline dim3 gT128(int M, int N) {
    return dim3((unsigned)((N + BNT2 - 1) / BNT2), (unsigned)((M + BMT - 1) / BMT), 1);
}

extern "C" void kernel_launch(void* const* d_in, const int* in_sizes, int n_in,
                              void* d_out, int out_size)
{
    const float* x     = (const float*)d_in[0];
    const float* Wq    = (const float*)d_in[1];
    const float* Wkv   = (const float*)d_in[2];
    const float* Wproj = (const float*)d_in[3];
    const float* bproj = (const float*)d_in[4];
    const float* dwcw  = (const float*)d_in[5];
    const float* dwcb  = (const float*)d_in[6];
    const float* an    = (const float*)d_in[7];
    const float* na    = (const float*)d_in[8];
    const float* ah    = (const float*)d_in[9];
    const float* aw    = (const float*)d_in[10];
    const float* ad    = (const float*)d_in[11];
    const float* ha    = (const float*)d_in[12];
    const float* wa    = (const float*)d_in[13];
    const float* da    = (const float*)d_in[14];
    float* out = (float*)d_out;

    void *pqkv, *pwq, *padla, *pb1, *pb2, *pb2t, *pav, *pavp, *plsp, *pao;
    cudaGetSymbolAddress(&pqkv, g_qkv);
    cudaGetSymbolAddress(&pwq, g_wqkv);
    cudaGetSymbolAddress(&padla, g_adla);
    cudaGetSymbolAddress(&pb1, g_bias1);
    cudaGetSymbolAddress(&pb2, g_bias2);
    cudaGetSymbolAddress(&pb2t, g_bias2t);
    cudaGetSymbolAddress(&pav, g_adlav);
    cudaGetSymbolAddress(&pavp, g_avp);
    cudaGetSymbolAddress(&plsp, g_lsp);
    cudaGetSymbolAddress(&pao, g_attnout);
    float* qkv  = (float*)pqkv;
    float* wqkv = (float*)pwq;
    float* adla = (float*)padla;
    float* b1   = (float*)pb1;
    float* b2   = (float*)pb2;
    float* b2t  = (float*)pb2t;
    float* av   = (float*)pav;
    float* avp  = (float*)pavp;
    float* lsp  = (float*)plsp;
    float* ao   = (float*)pao;

    cudaFuncSetAttribute(flash_core<0>, cudaFuncAttributeMaxDynamicSharedMemorySize, FSM);
    cudaFuncSetAttribute(flash_core<1>, cudaFuncAttributeMaxDynamicSharedMemorySize, FSM);

    // 0. pack [Wq|Wkv]
    pack_w<<<(DIMV * QKVS + 255) / 256, 256>>>(Wq, Wkv, wqkv);

    // 1. qkv = x @ [Wq|Wkv]   (one pass over x)
    tgemm128<<<gT128(BN_TOT, QKVS), 256>>>(BN_TOT, QKVS, DIMV,
        x,    DIMV, 1,
        wqkv, QKVS, 1,
        qkv,  QKVS, 1,
        nullptr, 0, 0, 1.f);

    // 2. adla pooling (from q slice of qkv)
    {
        long long tot = (long long)BATCH * ADLAV * DIMV;
        pool_kernel<<<(unsigned)((tot + 255) / 256), 256>>>(qkv, adla);
    }

    // 3. bias tables + transpose
    biasprep<<<HEADS * ADLAV, 256>>>(an, na, ah, aw, ad, ha, wa, da, b1, b2);
    transpose_b2<<<dim3((NTOK + 31) / 32, (ADLAV + 31) / 32, HEADS), dim3(32, 8)>>>(b2, b2t);

    // 4. fused attn1 (split-K): K = qkv+384, V = qkv+768
    flash_core<1><<<dim3((ADLAV + 127) / 128, BH, NSPLIT), 256, FSM>>>(
        adla,       (long long)ADLAV * DIMV, HD, DIMV,
        qkv + DIMV, (long long)NTOK * QKVS, HD, QKVS,
        qkv + DIMV, (long long)NTOK * QKVS, HD, QKVS, DIMV,
        b1,   (long long)ADLAV * NTOK, NTOK,
        avp,  0, 0, 0,
        lsp,
        ADLAV, NTOK);
    {
        long long tot = (long long)BH * ADLAV * HD;
        combine_av<<<(unsigned)((tot + 255) / 256), 256>>>(avp, lsp, av);
    }

    // 5. fused attn2: Q = qkv (q slice)
    flash_core<0><<<dim3((NTOK + 127) / 128, BH), 256, FSM>>>(
        qkv,  (long long)NTOK * QKVS, HD, QKVS,
        adla, (long long)ADLAV * DIMV, HD, DIMV,
        av,   (long long)HEADS * ADLAV * HD, (long long)ADLAV * HD, HD, 0,
        b2t,  (long long)NTOK * ADLAV, ADLAV,
        ao,   (long long)NTOK * DIMV, HD, DIMV,
        nullptr,
        NTOK, ADLAV);

    // 6. depthwise conv 3x3x3 of v, added into attnout
    {
        long long tot = (long long)BATCH * NTOK * DIMV;
        dwc_add<<<(unsigned)((tot + 255) / 256), 256>>>(qkv, dwcw, dwcb, ao);
    }

    // 7. final: out = attnout @ Wproj + bproj
    tgemm128<<<gT128(BN_TOT, DIMV), 256>>>(BN_TOT, DIMV, DIMV,
        ao,    DIMV, 1,
        Wproj, DIMV, 1,
        out,   DIMV, 1,
        bproj, 0, 1,
        1.f);

    (void)in_sizes; (void)n_in; (void)out_size;
}